// round 12
// baseline (speedup 1.0000x reference)
#include <cuda_runtime.h>

#define Bn 4
#define Nn 8192
#define Cin 64
#define Sn 2048
#define NS 32
#define R2 0.64f

// Scratch (device globals — no allocation allowed)
__device__ float g_F1[Bn * Nn * 128];    // per-point W1[:,3:]@features, [b][j][o]
__device__ int   g_idx[Bn * Sn * NS];
__device__ int   g_cnt[Bn * Sn];
__device__ float g_xs[Bn * Nn], g_ys[Bn * Nn], g_zs[Bn * Nn];  // SoA coords (orig order)
__device__ float g_sx[Bn * Nn], g_sy[Bn * Nn], g_sz[Bn * Nn];  // Morton-sorted coords
__device__ int   g_sid[Bn * Nn];                               // sorted -> original index
__device__ float g_W2T[128 * 256];       // W2 transposed: [c][o]

// ---------- packed f32x2 helpers ----------
__device__ __forceinline__ unsigned long long pk2(float a, float b) {
    unsigned long long u;
    asm("mov.b64 %0, {%1,%2};" : "=l"(u) : "f"(a), "f"(b));
    return u;
}
__device__ __forceinline__ void upk2(unsigned long long u, float& a, float& b) {
    asm("mov.b64 {%0,%1}, %2;" : "=f"(a), "=f"(b) : "l"(u));
}
__device__ __forceinline__ unsigned long long add2(unsigned long long a, unsigned long long b) {
    unsigned long long r; asm("add.rn.f32x2 %0, %1, %2;" : "=l"(r) : "l"(a), "l"(b)); return r;
}
__device__ __forceinline__ unsigned long long mul2(unsigned long long a, unsigned long long b) {
    unsigned long long r; asm("mul.rn.f32x2 %0, %1, %2;" : "=l"(r) : "l"(a), "l"(b)); return r;
}
__device__ __forceinline__ unsigned long long fma2(unsigned long long a, unsigned long long b,
                                                   unsigned long long c) {
    unsigned long long r; asm("fma.rn.f32x2 %0, %1, %2, %3;" : "=l"(r) : "l"(a), "l"(b), "l"(c)); return r;
}

// ---------------------------------------------------------------------------
// Prep: SoA transpose of xyz + W2 transpose
// ---------------------------------------------------------------------------
__global__ __launch_bounds__(256)
void prep_kernel(const float* __restrict__ xyz, const float* __restrict__ w2)
{
    const int i = blockIdx.x * 256 + threadIdx.x;
    if (i < Bn * Nn) {
        g_xs[i] = xyz[3 * i + 0];
        g_ys[i] = xyz[3 * i + 1];
        g_zs[i] = xyz[3 * i + 2];
    }
    if (i < 256 * 128) {
        const int o = i >> 7, c = i & 127;
        g_W2T[c * 256 + o] = w2[i];
    }
}

// ---------------------------------------------------------------------------
// Morton counting sort (perf-only permutation; results are exact regardless).
// ---------------------------------------------------------------------------
__device__ __forceinline__ int spread3(int v) {
    return (v & 1) | ((v & 2) << 2) | ((v & 4) << 4);
}

__global__ __launch_bounds__(1024, 1)
void fps_sort_kernel()
{
    const int b = blockIdx.x;
    const int base = b * Nn;
    const int t = threadIdx.x;

    __shared__ int h[512];
    __shared__ int off[512];

    if (t < 512) h[t] = 0;
    __syncthreads();

    float px[8], py[8], pz[8];
    int cell[8];
#pragma unroll
    for (int k = 0; k < 8; k++) {
        const int j = base + k * 1024 + t;
        float x = g_xs[j], y = g_ys[j], z = g_zs[j];
        px[k] = x; py[k] = y; pz[k] = z;
        int bx = min(7, max(0, (int)((x + 16.f) * 0.25f)));
        int by = min(7, max(0, (int)((y + 16.f) * 0.25f)));
        int bz = min(7, max(0, (int)((z + 16.f) * 0.25f)));
        cell[k] = (spread3(bx) << 2) | (spread3(by) << 1) | spread3(bz);
        atomicAdd(&h[cell[k]], 1);
    }
    __syncthreads();

    int cnt = 0;
    if (t < 512) cnt = h[t];
    for (int d = 1; d < 512; d <<= 1) {
        int u = 0;
        if (t < 512 && t >= d) u = h[t - d];
        __syncthreads();
        if (t < 512) h[t] += u;
        __syncthreads();
    }
    if (t < 512) off[t] = h[t] - cnt;
    __syncthreads();

#pragma unroll
    for (int k = 0; k < 8; k++) {
        int pos = atomicAdd(&off[cell[k]], 1);
        g_sx[base + pos] = px[k];
        g_sy[base + pos] = py[k];
        g_sz[base + pos] = pz[k];
        g_sid[base + pos] = k * 1024 + t;
    }
}

// ---------------------------------------------------------------------------
// FPS v5: exact bucket pruning + ONE barrier/iter. Candidates (val, idx,
// coords) double-buffered in shared; lane0 republishes its cached candidate
// every iteration so pruned warps stay valid in the current parity buffer.
// Every warp redundantly reduces the 32 slots — no serial warp0 phase, no
// global memory anywhere in the loop. jnp.argmax tie-break (lowest ORIGINAL
// index) preserved exactly via (idx<<5|slot) min-reduce on value-equal slots.
// ---------------------------------------------------------------------------
__global__ __launch_bounds__(1024, 1)
void fps_kernel(float* __restrict__ new_xyz)
{
    const int b = blockIdx.x;
    const int base = b * Nn;
    const int t = threadIdx.x;
    const int lane = t & 31;
    const int w = t >> 5;

    float dst[8];
    int gid[8];
    unsigned long long X2[4], Y2[4], Z2[4];
#pragma unroll
    for (int g = 0; g < 4; g++) {
        const int j0 = base + w * 256 + (2 * g) * 32 + lane;
        const int j1 = base + w * 256 + (2 * g + 1) * 32 + lane;
        X2[g] = pk2(g_sx[j0], g_sx[j1]);
        Y2[g] = pk2(g_sy[j0], g_sy[j1]);
        Z2[g] = pk2(g_sz[j0], g_sz[j1]);
        gid[2 * g]     = g_sid[j0];
        gid[2 * g + 1] = g_sid[j1];
        dst[2 * g] = 1e10f;
        dst[2 * g + 1] = 1e10f;
    }

    // warp bbox from packed registers (one-time)
    float xmn, xmx, ymn, ymx, zmn, zmx;
    {
        float a, c;
        upk2(X2[0], a, c); xmn = fminf(a, c); xmx = fmaxf(a, c);
        upk2(Y2[0], a, c); ymn = fminf(a, c); ymx = fmaxf(a, c);
        upk2(Z2[0], a, c); zmn = fminf(a, c); zmx = fmaxf(a, c);
#pragma unroll
        for (int g = 1; g < 4; g++) {
            upk2(X2[g], a, c); xmn = fminf(xmn, fminf(a, c)); xmx = fmaxf(xmx, fmaxf(a, c));
            upk2(Y2[g], a, c); ymn = fminf(ymn, fminf(a, c)); ymx = fmaxf(ymx, fmaxf(a, c));
            upk2(Z2[g], a, c); zmn = fminf(zmn, fminf(a, c)); zmx = fmaxf(zmx, fmaxf(a, c));
        }
#pragma unroll
        for (int o = 16; o > 0; o >>= 1) {
            xmn = fminf(xmn, __shfl_xor_sync(0xffffffffu, xmn, o));
            xmx = fmaxf(xmx, __shfl_xor_sync(0xffffffffu, xmx, o));
            ymn = fminf(ymn, __shfl_xor_sync(0xffffffffu, ymn, o));
            ymx = fmaxf(ymx, __shfl_xor_sync(0xffffffffu, ymx, o));
            zmn = fminf(zmn, __shfl_xor_sync(0xffffffffu, zmn, o));
            zmx = fmaxf(zmx, __shfl_xor_sync(0xffffffffu, zmx, o));
        }
    }

    __shared__ float sval[2][32];
    __shared__ int   skey[2][32];
    __shared__ float scx[2][32], scy[2][32], scz[2][32];

    float cand_v = -1.f;
    int   cand_i = 0x7fffffff;
    float cand_x = 0.f, cand_y = 0.f, cand_z = 0.f;
    float wmax = 1e10f;
    float qx = g_xs[base], qy = g_ys[base], qz = g_zs[base];
    if (t == 0) {
        new_xyz[(b * Sn) * 3 + 0] = qx;
        new_xyz[(b * Sn) * 3 + 1] = qy;
        new_xyz[(b * Sn) * 3 + 2] = qz;
    }

    for (int i = 1; i < Sn; i++) {
        const int p = i & 1;

        // exact prune: distance from q to warp bbox
        float dxl = fmaxf(0.f, fmaxf(xmn - qx, qx - xmx));
        float dyl = fmaxf(0.f, fmaxf(ymn - qy, qy - ymx));
        float dzl = fmaxf(0.f, fmaxf(zmn - qz, qz - zmx));
        float dbox = dxl * dxl + dyl * dyl + dzl * dzl;

        if (dbox < wmax) {
            const unsigned long long nqx = pk2(-qx, -qx);
            const unsigned long long nqy = pk2(-qy, -qy);
            const unsigned long long nqz = pk2(-qz, -qz);
#pragma unroll
            for (int g = 0; g < 4; g++) {
                unsigned long long dx = add2(X2[g], nqx);
                unsigned long long dy = add2(Y2[g], nqy);
                unsigned long long dz = add2(Z2[g], nqz);
                unsigned long long d  = fma2(dx, dx, fma2(dy, dy, mul2(dz, dz)));
                float dlo, dhi; upk2(d, dlo, dhi);
                dst[2 * g]     = fminf(dst[2 * g], dlo);
                dst[2 * g + 1] = fminf(dst[2 * g + 1], dhi);
            }
            float m0 = fmaxf(dst[0], dst[1]), m1 = fmaxf(dst[2], dst[3]);
            float m2 = fmaxf(dst[4], dst[5]), m3 = fmaxf(dst[6], dst[7]);
            float vm = fmaxf(fmaxf(m0, m1), fmaxf(m2, m3));

            unsigned gmb = __reduce_max_sync(0xffffffffu, __float_as_uint(vm));
            float gmw = __uint_as_float(gmb);

            // per-lane best (lowest original index) + its slot
            int candg = 0x7fffffff;
            int candk = 0;
#pragma unroll
            for (int k = 0; k < 8; k++)
                if (dst[k] == gmw && gid[k] < candg) { candg = gid[k]; candk = k; }
            int widx = (int)__reduce_min_sync(0xffffffffu, (unsigned)candg);

            // owning lane & coords from packed registers
            unsigned msk = __ballot_sync(0xffffffffu, candg == widx);
            int src = __ffs(msk) - 1;
            unsigned long long PX = X2[0], PY = Y2[0], PZ = Z2[0];
#pragma unroll
            for (int g = 1; g < 4; g++)
                if ((candk >> 1) == g) { PX = X2[g]; PY = Y2[g]; PZ = Z2[g]; }
            float xlo, xhi, ylo, yhi, zlo, zhi;
            upk2(PX, xlo, xhi); upk2(PY, ylo, yhi); upk2(PZ, zlo, zhi);
            float cx = (candk & 1) ? xhi : xlo;
            float cy = (candk & 1) ? yhi : ylo;
            float cz = (candk & 1) ? zhi : zlo;
            cand_x = __shfl_sync(0xffffffffu, cx, src);
            cand_y = __shfl_sync(0xffffffffu, cy, src);
            cand_z = __shfl_sync(0xffffffffu, cz, src);
            cand_v = gmw;
            cand_i = widx;
            wmax = gmw;
        }
        // ALWAYS republish cached candidate into the current parity buffer
        if (lane == 0) {
            sval[p][w] = cand_v; skey[p][w] = cand_i;
            scx[p][w] = cand_x; scy[p][w] = cand_y; scz[p][w] = cand_z;
        }
        __syncthreads();

        // every warp reduces the 32 slots
        float v  = sval[p][lane];
        int  idv = skey[p][lane];
        unsigned gmb2 = __reduce_max_sync(0xffffffffu, __float_as_uint(v));
        int key = (__float_as_uint(v) == gmb2) ? ((idv << 5) | lane) : 0x7fffffff;
        int kmin = (int)__reduce_min_sync(0xffffffffu, (unsigned)key);
        const int ws = kmin & 31;

        qx = scx[p][ws]; qy = scy[p][ws]; qz = scz[p][ws];
        if (t == 0) {
            new_xyz[(b * Sn + i) * 3 + 0] = qx;
            new_xyz[(b * Sn + i) * 3 + 1] = qy;
            new_xyz[(b * Sn + i) * 3 + 2] = qz;
        }
    }
}

// ---------------------------------------------------------------------------
// F1 precompute: F1[b][j][o] = sum_c W1[o][3+c] * features[b][c][j]
// ---------------------------------------------------------------------------
__global__ __launch_bounds__(256)
void f1_kernel(const float* __restrict__ features, const float* __restrict__ w1)
{
    const int b  = blockIdx.x >> 7;
    const int jt = blockIdx.x & 127;
    const int j0 = jt * 64;
    const int t  = threadIdx.x;
    const int o  = t & 127;
    const int jh = t >> 7;

    __shared__ float sf[64][64];
    for (int idx = t; idx < 64 * 64; idx += 256) {
        int c = idx >> 6, j = idx & 63;
        sf[c][j] = features[((size_t)b * Cin + c) * Nn + j0 + j];
    }
    float wr[64];
#pragma unroll
    for (int c = 0; c < 64; c++) wr[c] = w1[o * 67 + 3 + c];
    __syncthreads();

    for (int jg = 0; jg < 8; jg++) {
        const int jb = jh * 32 + jg * 4;
        float a0 = 0.f, a1 = 0.f, a2 = 0.f, a3 = 0.f;
#pragma unroll
        for (int c = 0; c < 64; c++) {
            float4 f = *(const float4*)&sf[c][jb];
            a0 += wr[c] * f.x; a1 += wr[c] * f.y;
            a2 += wr[c] * f.z; a3 += wr[c] * f.w;
        }
        const int j = j0 + jb;
        g_F1[((size_t)b * Nn + j + 0) * 128 + o] = a0;
        g_F1[((size_t)b * Nn + j + 1) * 128 + o] = a1;
        g_F1[((size_t)b * Nn + j + 2) * 128 + o] = a2;
        g_F1[((size_t)b * Nn + j + 3) * 128 + o] = a3;
    }
}

// ---------------------------------------------------------------------------
// Ball query: one warp per query, SoA coalesced loads.
// ---------------------------------------------------------------------------
__global__ __launch_bounds__(256)
void bq_kernel(const float* __restrict__ new_xyz)
{
    const int gw   = (blockIdx.x * blockDim.x + threadIdx.x) >> 5;
    const int lane = threadIdx.x & 31;
    if (gw >= Bn * Sn) return;
    const int b = gw >> 11;
    const int base = b * Nn;

    const float qx = new_xyz[gw * 3 + 0];
    const float qy = new_xyz[gw * 3 + 1];
    const float qz = new_xyz[gw * 3 + 2];

    int cnt = 0;
    int myidx = 0;
    for (int bs = 0; bs < Nn; bs += 32) {
        const int j = base + bs + lane;
        float dx = g_xs[j] - qx;
        float dy = g_ys[j] - qy;
        float dz = g_zs[j] - qz;
        float d2 = dx * dx + dy * dy + dz * dz;
        unsigned m = __ballot_sync(0xffffffffu, d2 < R2);
        while (m && cnt < NS) {
            int l = __ffs(m) - 1;
            m &= m - 1;
            if (lane == cnt) myidx = bs + l;
            cnt++;
        }
        if (cnt >= NS) break;
    }
    int first = __shfl_sync(0xffffffffu, myidx, 0);
    if (lane >= cnt) myidx = (cnt > 0) ? first : 0;
    g_idx[gw * NS + lane] = myidx;
    if (lane == 0) g_cnt[gw] = cnt;
}

// ---------------------------------------------------------------------------
// MLP + maxpool: one block per query, 256 threads, thread t owns output o=t.
// ---------------------------------------------------------------------------
__global__ __launch_bounds__(256, 2)
void mlp_kernel(const float* __restrict__ new_xyz,
                const float* __restrict__ w1, const float* __restrict__ b1,
                const float* __restrict__ b2, float* __restrict__ pooled)
{
    const int q = blockIdx.x;
    const int b = q >> 11;
    const int s = q & 2047;
    const int t = threadIdx.x;

    __shared__ float H1[NS][128];
    __shared__ float rx[NS], ry[NS], rz[NS];
    __shared__ int   gi[NS];
    __shared__ int   scnt;

    if (t < NS) {
        const int id = g_idx[q * NS + t];
        gi[t] = id;
        const int base = b * Nn;
        rx[t] = g_xs[base + id] - new_xyz[q * 3 + 0];
        ry[t] = g_ys[base + id] - new_xyz[q * 3 + 1];
        rz[t] = g_zs[base + id] - new_xyz[q * 3 + 2];
    }
    if (t == 0) scnt = g_cnt[q];
    __syncthreads();

    const int cnt = scnt;

    // Stage 1: H1[n][o] = relu(F1[id][o] + W1xyz . rel + b1[o])
    {
        const int o  = t & 127;
        const int n0 = (t >> 7) * 16;
        const float w1x = w1[o * 67 + 0];
        const float w1y = w1[o * 67 + 1];
        const float w1z = w1[o * 67 + 2];
        const float bb  = b1[o];
        for (int n = n0; n < n0 + 16; n++) {
            float v;
            if (cnt > 0) {
                const int id = gi[n];
                float f = g_F1[((size_t)b * Nn + id) * 128 + o];
                v = f + w1x * rx[n] + w1y * ry[n] + w1z * rz[n] + bb;
            } else {
                v = bb;
            }
            H1[n][o] = fmaxf(v, 0.f);
        }
    }
    __syncthreads();

    // Stage 2: acc[n] = dot(W2[t], H1[n]); max over n.
    float acc[32];
#pragma unroll
    for (int n = 0; n < 32; n++) acc[n] = 0.f;

    for (int cc = 0; cc < 128; cc += 16) {
        float wv[16];
#pragma unroll
        for (int i = 0; i < 16; i++)
            wv[i] = __ldg(&g_W2T[(cc + i) * 256 + t]);
#pragma unroll
        for (int n = 0; n < 32; n++) {
            const float* h = &H1[n][cc];
            float4 h0 = *(const float4*)(h);
            float4 h1 = *(const float4*)(h + 4);
            float4 h2 = *(const float4*)(h + 8);
            float4 h3 = *(const float4*)(h + 12);
            float a = acc[n];
            a = fmaf(wv[0],  h0.x, a); a = fmaf(wv[1],  h0.y, a);
            a = fmaf(wv[2],  h0.z, a); a = fmaf(wv[3],  h0.w, a);
            a = fmaf(wv[4],  h1.x, a); a = fmaf(wv[5],  h1.y, a);
            a = fmaf(wv[6],  h1.z, a); a = fmaf(wv[7],  h1.w, a);
            a = fmaf(wv[8],  h2.x, a); a = fmaf(wv[9],  h2.y, a);
            a = fmaf(wv[10], h2.z, a); a = fmaf(wv[11], h2.w, a);
            a = fmaf(wv[12], h3.x, a); a = fmaf(wv[13], h3.y, a);
            a = fmaf(wv[14], h3.z, a); a = fmaf(wv[15], h3.w, a);
            acc[n] = a;
        }
    }

    const float bb2 = b2[t];
    float mx = 0.f;
#pragma unroll
    for (int n = 0; n < 32; n++)
        mx = fmaxf(mx, fmaxf(acc[n] + bb2, 0.f));
    pooled[((size_t)b * 256 + t) * Sn + s] = mx;
}

// ---------------------------------------------------------------------------
extern "C" void kernel_launch(void* const* d_in, const int* in_sizes, int n_in,
                              void* d_out, int out_size)
{
    const float* xyz      = (const float*)d_in[0];
    const float* features = (const float*)d_in[1];
    const float* w1       = (const float*)d_in[2];
    const float* b1       = (const float*)d_in[3];
    const float* w2       = (const float*)d_in[4];
    const float* b2       = (const float*)d_in[5];

    float* out     = (float*)d_out;
    float* new_xyz = out;
    float* pooled  = out + Bn * Sn * 3;

    prep_kernel<<<128, 256>>>(xyz, w2);
    fps_sort_kernel<<<Bn, 1024>>>();
    f1_kernel<<<Bn * 128, 256>>>(features, w1);
    fps_kernel<<<Bn, 1024>>>(new_xyz);
    bq_kernel<<<(Bn * Sn * 32 + 255) / 256, 256>>>(new_xyz);
    mlp_kernel<<<Bn * Sn, 256>>>(new_xyz, w1, b1, b2, pooled);
}

// round 13
// speedup vs baseline: 1.3929x; 1.3929x over previous
#include <cuda_runtime.h>

#define Bn 4
#define Nn 8192
#define Cin 64
#define Sn 2048
#define NS 32
#define R2 0.64f

// Scratch (device globals — no allocation allowed)
__device__ float g_F1[Bn * Nn * 128];    // per-point W1[:,3:]@features, [b][j][o]
__device__ int   g_idx[Bn * Sn * NS];
__device__ int   g_cnt[Bn * Sn];
__device__ float g_xs[Bn * Nn], g_ys[Bn * Nn], g_zs[Bn * Nn];  // SoA coords (orig order)
__device__ float g_sx[Bn * Nn], g_sy[Bn * Nn], g_sz[Bn * Nn];  // Morton-sorted coords
__device__ int   g_sid[Bn * Nn];                               // sorted -> original index
__device__ float g_W2T[128 * 256];       // W2 transposed: [c][o]

// ---------- packed f32x2 helpers ----------
__device__ __forceinline__ unsigned long long pk2(float a, float b) {
    unsigned long long u;
    asm("mov.b64 %0, {%1,%2};" : "=l"(u) : "f"(a), "f"(b));
    return u;
}
__device__ __forceinline__ void upk2(unsigned long long u, float& a, float& b) {
    asm("mov.b64 {%0,%1}, %2;" : "=f"(a), "=f"(b) : "l"(u));
}
__device__ __forceinline__ unsigned long long add2(unsigned long long a, unsigned long long b) {
    unsigned long long r; asm("add.rn.f32x2 %0, %1, %2;" : "=l"(r) : "l"(a), "l"(b)); return r;
}
__device__ __forceinline__ unsigned long long mul2(unsigned long long a, unsigned long long b) {
    unsigned long long r; asm("mul.rn.f32x2 %0, %1, %2;" : "=l"(r) : "l"(a), "l"(b)); return r;
}
__device__ __forceinline__ unsigned long long fma2(unsigned long long a, unsigned long long b,
                                                   unsigned long long c) {
    unsigned long long r; asm("fma.rn.f32x2 %0, %1, %2, %3;" : "=l"(r) : "l"(a), "l"(b), "l"(c)); return r;
}

// ---------------------------------------------------------------------------
// Prep: SoA transpose of xyz + W2 transpose
// ---------------------------------------------------------------------------
__global__ __launch_bounds__(256)
void prep_kernel(const float* __restrict__ xyz, const float* __restrict__ w2)
{
    const int i = blockIdx.x * 256 + threadIdx.x;
    if (i < Bn * Nn) {
        g_xs[i] = xyz[3 * i + 0];
        g_ys[i] = xyz[3 * i + 1];
        g_zs[i] = xyz[3 * i + 2];
    }
    if (i < 256 * 128) {
        const int o = i >> 7, c = i & 127;
        g_W2T[c * 256 + o] = w2[i];
    }
}

// ---------------------------------------------------------------------------
// Morton counting sort (perf-only permutation; results are exact regardless).
// ---------------------------------------------------------------------------
__device__ __forceinline__ int spread3(int v) {
    return (v & 1) | ((v & 2) << 2) | ((v & 4) << 4);
}

__global__ __launch_bounds__(1024, 1)
void fps_sort_kernel()
{
    const int b = blockIdx.x;
    const int base = b * Nn;
    const int t = threadIdx.x;

    __shared__ int h[512];
    __shared__ int off[512];

    if (t < 512) h[t] = 0;
    __syncthreads();

    float px[8], py[8], pz[8];
    int cell[8];
#pragma unroll
    for (int k = 0; k < 8; k++) {
        const int j = base + k * 1024 + t;
        float x = g_xs[j], y = g_ys[j], z = g_zs[j];
        px[k] = x; py[k] = y; pz[k] = z;
        int bx = min(7, max(0, (int)((x + 16.f) * 0.25f)));
        int by = min(7, max(0, (int)((y + 16.f) * 0.25f)));
        int bz = min(7, max(0, (int)((z + 16.f) * 0.25f)));
        cell[k] = (spread3(bx) << 2) | (spread3(by) << 1) | spread3(bz);
        atomicAdd(&h[cell[k]], 1);
    }
    __syncthreads();

    int cnt = 0;
    if (t < 512) cnt = h[t];
    for (int d = 1; d < 512; d <<= 1) {
        int u = 0;
        if (t < 512 && t >= d) u = h[t - d];
        __syncthreads();
        if (t < 512) h[t] += u;
        __syncthreads();
    }
    if (t < 512) off[t] = h[t] - cnt;
    __syncthreads();

#pragma unroll
    for (int k = 0; k < 8; k++) {
        int pos = atomicAdd(&off[cell[k]], 1);
        g_sx[base + pos] = px[k];
        g_sy[base + pos] = py[k];
        g_sz[base + pos] = pz[k];
        g_sid[base + pos] = k * 1024 + t;
    }
}

// ---------------------------------------------------------------------------
// FPS (R6 skeleton) + 96KB shared cache of ORIGINAL-order coords so the
// per-iteration winner lookup is broadcast LDS instead of scattered LDG.
// Exact bucket pruning; jnp.argmax lowest-index tie-break preserved exactly.
// ---------------------------------------------------------------------------
extern __shared__ float fps_smem[];   // [3 * Nn] : xc | yc | zc

__global__ __launch_bounds__(1024, 1)
void fps_kernel(float* __restrict__ new_xyz)
{
    const int b = blockIdx.x;
    const int base = b * Nn;
    const int t = threadIdx.x;
    const int lane = t & 31;
    const int w = t >> 5;

    float* xc = fps_smem;
    float* yc = fps_smem + Nn;
    float* zc = fps_smem + 2 * Nn;

    // fill shared coord cache (original order, coalesced)
#pragma unroll
    for (int k = 0; k < 8; k++) {
        const int j = k * 1024 + t;
        xc[j] = g_xs[base + j];
        yc[j] = g_ys[base + j];
        zc[j] = g_zs[base + j];
    }

    float dst[8];
    int gid[8];
    float x[8], y[8], z[8];
#pragma unroll
    for (int k = 0; k < 8; k++) {
        const int j = base + w * 256 + k * 32 + lane;
        x[k] = g_sx[j]; y[k] = g_sy[j]; z[k] = g_sz[j];
        gid[k] = g_sid[j];
        dst[k] = 1e10f;
    }

    // warp bbox (one-time)
    float xmn = x[0], xmx = x[0], ymn = y[0], ymx = y[0], zmn = z[0], zmx = z[0];
#pragma unroll
    for (int k = 1; k < 8; k++) {
        xmn = fminf(xmn, x[k]); xmx = fmaxf(xmx, x[k]);
        ymn = fminf(ymn, y[k]); ymx = fmaxf(ymx, y[k]);
        zmn = fminf(zmn, z[k]); zmx = fmaxf(zmx, z[k]);
    }
#pragma unroll
    for (int o = 16; o > 0; o >>= 1) {
        xmn = fminf(xmn, __shfl_xor_sync(0xffffffffu, xmn, o));
        xmx = fmaxf(xmx, __shfl_xor_sync(0xffffffffu, xmx, o));
        ymn = fminf(ymn, __shfl_xor_sync(0xffffffffu, ymn, o));
        ymx = fmaxf(ymx, __shfl_xor_sync(0xffffffffu, ymx, o));
        zmn = fminf(zmn, __shfl_xor_sync(0xffffffffu, zmn, o));
        zmx = fmaxf(zmx, __shfl_xor_sync(0xffffffffu, zmx, o));
    }

    unsigned long long X2[4], Y2[4], Z2[4];
#pragma unroll
    for (int g = 0; g < 4; g++) {
        X2[g] = pk2(x[2 * g], x[2 * g + 1]);
        Y2[g] = pk2(y[2 * g], y[2 * g + 1]);
        Z2[g] = pk2(z[2 * g], z[2 * g + 1]);
    }

    __shared__ float sval[32];
    __shared__ int   sidx[32];
    __shared__ int   sgdx;

    float wmax = 1e10f;
    __syncthreads();   // coord cache ready
    float qx = xc[0], qy = yc[0], qz = zc[0];
    if (t == 0) {
        new_xyz[(b * Sn) * 3 + 0] = qx;
        new_xyz[(b * Sn) * 3 + 1] = qy;
        new_xyz[(b * Sn) * 3 + 2] = qz;
    }

    for (int i = 1; i < Sn; i++) {
        // exact prune test: distance from q to warp bbox
        float dxl = fmaxf(0.f, fmaxf(xmn - qx, qx - xmx));
        float dyl = fmaxf(0.f, fmaxf(ymn - qy, qy - ymx));
        float dzl = fmaxf(0.f, fmaxf(zmn - qz, qz - zmx));
        float dbox = dxl * dxl + dyl * dyl + dzl * dzl;

        if (dbox < wmax) {
            const unsigned long long nqx = pk2(-qx, -qx);
            const unsigned long long nqy = pk2(-qy, -qy);
            const unsigned long long nqz = pk2(-qz, -qz);
#pragma unroll
            for (int g = 0; g < 4; g++) {
                unsigned long long dx = add2(X2[g], nqx);
                unsigned long long dy = add2(Y2[g], nqy);
                unsigned long long dz = add2(Z2[g], nqz);
                unsigned long long d  = fma2(dx, dx, fma2(dy, dy, mul2(dz, dz)));
                float dlo, dhi; upk2(d, dlo, dhi);
                dst[2 * g]     = fminf(dst[2 * g], dlo);
                dst[2 * g + 1] = fminf(dst[2 * g + 1], dhi);
            }
            float m0 = fmaxf(dst[0], dst[1]), m1 = fmaxf(dst[2], dst[3]);
            float m2 = fmaxf(dst[4], dst[5]), m3 = fmaxf(dst[6], dst[7]);
            float vm = fmaxf(fmaxf(m0, m1), fmaxf(m2, m3));

            unsigned gmb = __reduce_max_sync(0xffffffffu, __float_as_uint(vm));
            float gmw = __uint_as_float(gmb);
            int cand = 0x7fffffff;
#pragma unroll
            for (int k = 0; k < 8; k++)
                if (dst[k] == gmw) cand = min(cand, gid[k]);
            int widx = (int)__reduce_min_sync(0xffffffffu, (unsigned)cand);
            if (lane == 0) { sval[w] = gmw; sidx[w] = widx; }
            wmax = gmw;
        }
        __syncthreads();
        if (w == 0) {
            float v = sval[lane];
            int idv = sidx[lane];
            unsigned gmb = __reduce_max_sync(0xffffffffu, __float_as_uint(v));
            int cand = (__float_as_uint(v) == gmb) ? idv : 0x7fffffff;
            int gdx = (int)__reduce_min_sync(0xffffffffu, (unsigned)cand);
            if (lane == 0) {
                sgdx = gdx;
                new_xyz[(b * Sn + i) * 3 + 0] = xc[gdx];
                new_xyz[(b * Sn + i) * 3 + 1] = yc[gdx];
                new_xyz[(b * Sn + i) * 3 + 2] = zc[gdx];
            }
        }
        __syncthreads();
        const int gq = sgdx;
        qx = xc[gq]; qy = yc[gq]; qz = zc[gq];   // broadcast LDS, conflict-free
    }
}

// ---------------------------------------------------------------------------
// F1 precompute: F1[b][j][o] = sum_c W1[o][3+c] * features[b][c][j]
// ---------------------------------------------------------------------------
__global__ __launch_bounds__(256)
void f1_kernel(const float* __restrict__ features, const float* __restrict__ w1)
{
    const int b  = blockIdx.x >> 7;
    const int jt = blockIdx.x & 127;
    const int j0 = jt * 64;
    const int t  = threadIdx.x;
    const int o  = t & 127;
    const int jh = t >> 7;

    __shared__ float sf[64][64];
    for (int idx = t; idx < 64 * 64; idx += 256) {
        int c = idx >> 6, j = idx & 63;
        sf[c][j] = features[((size_t)b * Cin + c) * Nn + j0 + j];
    }
    float wr[64];
#pragma unroll
    for (int c = 0; c < 64; c++) wr[c] = w1[o * 67 + 3 + c];
    __syncthreads();

    for (int jg = 0; jg < 8; jg++) {
        const int jb = jh * 32 + jg * 4;
        float a0 = 0.f, a1 = 0.f, a2 = 0.f, a3 = 0.f;
#pragma unroll
        for (int c = 0; c < 64; c++) {
            float4 f = *(const float4*)&sf[c][jb];
            a0 += wr[c] * f.x; a1 += wr[c] * f.y;
            a2 += wr[c] * f.z; a3 += wr[c] * f.w;
        }
        const int j = j0 + jb;
        g_F1[((size_t)b * Nn + j + 0) * 128 + o] = a0;
        g_F1[((size_t)b * Nn + j + 1) * 128 + o] = a1;
        g_F1[((size_t)b * Nn + j + 2) * 128 + o] = a2;
        g_F1[((size_t)b * Nn + j + 3) * 128 + o] = a3;
    }
}

// ---------------------------------------------------------------------------
// Ball query: one warp per query, SoA coalesced loads.
// ---------------------------------------------------------------------------
__global__ __launch_bounds__(256)
void bq_kernel(const float* __restrict__ new_xyz)
{
    const int gw   = (blockIdx.x * blockDim.x + threadIdx.x) >> 5;
    const int lane = threadIdx.x & 31;
    if (gw >= Bn * Sn) return;
    const int b = gw >> 11;
    const int base = b * Nn;

    const float qx = new_xyz[gw * 3 + 0];
    const float qy = new_xyz[gw * 3 + 1];
    const float qz = new_xyz[gw * 3 + 2];

    int cnt = 0;
    int myidx = 0;
    for (int bs = 0; bs < Nn; bs += 32) {
        const int j = base + bs + lane;
        float dx = g_xs[j] - qx;
        float dy = g_ys[j] - qy;
        float dz = g_zs[j] - qz;
        float d2 = dx * dx + dy * dy + dz * dz;
        unsigned m = __ballot_sync(0xffffffffu, d2 < R2);
        while (m && cnt < NS) {
            int l = __ffs(m) - 1;
            m &= m - 1;
            if (lane == cnt) myidx = bs + l;
            cnt++;
        }
        if (cnt >= NS) break;
    }
    int first = __shfl_sync(0xffffffffu, myidx, 0);
    if (lane >= cnt) myidx = (cnt > 0) ? first : 0;
    g_idx[gw * NS + lane] = myidx;
    if (lane == 0) g_cnt[gw] = cnt;
}

// ---------------------------------------------------------------------------
// MLP + maxpool: one block per query, 256 threads, thread t owns output o=t.
// ---------------------------------------------------------------------------
__global__ __launch_bounds__(256, 2)
void mlp_kernel(const float* __restrict__ new_xyz,
                const float* __restrict__ w1, const float* __restrict__ b1,
                const float* __restrict__ b2, float* __restrict__ pooled)
{
    const int q = blockIdx.x;
    const int b = q >> 11;
    const int s = q & 2047;
    const int t = threadIdx.x;

    __shared__ float H1[NS][128];
    __shared__ float rx[NS], ry[NS], rz[NS];
    __shared__ int   gi[NS];
    __shared__ int   scnt;

    if (t < NS) {
        const int id = g_idx[q * NS + t];
        gi[t] = id;
        const int base = b * Nn;
        rx[t] = g_xs[base + id] - new_xyz[q * 3 + 0];
        ry[t] = g_ys[base + id] - new_xyz[q * 3 + 1];
        rz[t] = g_zs[base + id] - new_xyz[q * 3 + 2];
    }
    if (t == 0) scnt = g_cnt[q];
    __syncthreads();

    const int cnt = scnt;

    // Stage 1: H1[n][o] = relu(F1[id][o] + W1xyz . rel + b1[o])
    {
        const int o  = t & 127;
        const int n0 = (t >> 7) * 16;
        const float w1x = w1[o * 67 + 0];
        const float w1y = w1[o * 67 + 1];
        const float w1z = w1[o * 67 + 2];
        const float bb  = b1[o];
        for (int n = n0; n < n0 + 16; n++) {
            float v;
            if (cnt > 0) {
                const int id = gi[n];
                float f = g_F1[((size_t)b * Nn + id) * 128 + o];
                v = f + w1x * rx[n] + w1y * ry[n] + w1z * rz[n] + bb;
            } else {
                v = bb;
            }
            H1[n][o] = fmaxf(v, 0.f);
        }
    }
    __syncthreads();

    // Stage 2: acc[n] = dot(W2[t], H1[n]); max over n.
    float acc[32];
#pragma unroll
    for (int n = 0; n < 32; n++) acc[n] = 0.f;

    for (int cc = 0; cc < 128; cc += 16) {
        float wv[16];
#pragma unroll
        for (int i = 0; i < 16; i++)
            wv[i] = __ldg(&g_W2T[(cc + i) * 256 + t]);
#pragma unroll
        for (int n = 0; n < 32; n++) {
            const float* h = &H1[n][cc];
            float4 h0 = *(const float4*)(h);
            float4 h1 = *(const float4*)(h + 4);
            float4 h2 = *(const float4*)(h + 8);
            float4 h3 = *(const float4*)(h + 12);
            float a = acc[n];
            a = fmaf(wv[0],  h0.x, a); a = fmaf(wv[1],  h0.y, a);
            a = fmaf(wv[2],  h0.z, a); a = fmaf(wv[3],  h0.w, a);
            a = fmaf(wv[4],  h1.x, a); a = fmaf(wv[5],  h1.y, a);
            a = fmaf(wv[6],  h1.z, a); a = fmaf(wv[7],  h1.w, a);
            a = fmaf(wv[8],  h2.x, a); a = fmaf(wv[9],  h2.y, a);
            a = fmaf(wv[10], h2.z, a); a = fmaf(wv[11], h2.w, a);
            a = fmaf(wv[12], h3.x, a); a = fmaf(wv[13], h3.y, a);
            a = fmaf(wv[14], h3.z, a); a = fmaf(wv[15], h3.w, a);
            acc[n] = a;
        }
    }

    const float bb2 = b2[t];
    float mx = 0.f;
#pragma unroll
    for (int n = 0; n < 32; n++)
        mx = fmaxf(mx, fmaxf(acc[n] + bb2, 0.f));
    pooled[((size_t)b * 256 + t) * Sn + s] = mx;
}

// ---------------------------------------------------------------------------
extern "C" void kernel_launch(void* const* d_in, const int* in_sizes, int n_in,
                              void* d_out, int out_size)
{
    const float* xyz      = (const float*)d_in[0];
    const float* features = (const float*)d_in[1];
    const float* w1       = (const float*)d_in[2];
    const float* b1       = (const float*)d_in[3];
    const float* w2       = (const float*)d_in[4];
    const float* b2       = (const float*)d_in[5];

    float* out     = (float*)d_out;
    float* new_xyz = out;
    float* pooled  = out + Bn * Sn * 3;

    const int fps_smem_bytes = 3 * Nn * (int)sizeof(float);   // 96 KB
    static int attr_set = 0;
    if (!attr_set) {
        cudaFuncSetAttribute(fps_kernel,
                             cudaFuncAttributeMaxDynamicSharedMemorySize,
                             fps_smem_bytes);
        attr_set = 1;
    }

    prep_kernel<<<128, 256>>>(xyz, w2);
    fps_sort_kernel<<<Bn, 1024>>>();
    f1_kernel<<<Bn * 128, 256>>>(features, w1);
    fps_kernel<<<Bn, 1024, fps_smem_bytes>>>(new_xyz);
    bq_kernel<<<(Bn * Sn * 32 + 255) / 256, 256>>>(new_xyz);
    mlp_kernel<<<Bn * Sn, 256>>>(new_xyz, w1, b1, b2, pooled);
}